// round 9
// baseline (speedup 1.0000x reference)
#include <cuda_runtime.h>
#include <cuda_bf16.h>
#include <math.h>
#include <stdint.h>

#define BB 8
#define NN 2048
#define FF 64

typedef unsigned long long u64;
typedef unsigned int u32;

// -------------------- device scratch --------------------
__device__ __align__(16) float g_f1[BB * NN];     // prescaled by log2(e)
__device__ __align__(16) float g_f2[BB * NN];     // prescaled by log2(e)
__device__ __align__(16) u32 g_hTh[BB * FF * (NN / 2)];
__device__ __align__(16) u32 g_hTl[BB * FF * (NN / 2)];
__device__ __align__(16) uint4 g_mask[BB * NN * 16];

// -------------------- PTX helpers --------------------
#define FMA2(d, a, b, c) \
    asm("fma.rn.f32x2 %0,%1,%2,%3;" : "=l"(d) : "l"(a), "l"(b), "l"(c))
#define UNPACK2(lo, hi, s) \
    asm("mov.b64 {%0,%1},%2;" : "=f"(lo), "=f"(hi) : "l"(s))

__device__ __forceinline__ float ex2(float x) {
    float r; asm("ex2.approx.ftz.f32 %0,%1;" : "=f"(r) : "f"(x)); return r;
}
__device__ __forceinline__ u32 smem_u32(const void* p) {
    u32 a;
    asm("{.reg .u64 t; cvta.to.shared.u64 t, %1; cvt.u32.u64 %0, t;}"
        : "=r"(a) : "l"(p));
    return a;
}

#define CPASYNC16(saddr, gptr) \
    asm volatile("cp.async.ca.shared.global [%0], [%1], 16;" \
                 :: "r"(saddr), "l"(gptr) : "memory")
#define CPCOMMIT() asm volatile("cp.async.commit_group;" ::: "memory")
#define CPWAIT0()  asm volatile("cp.async.wait_group 0;" ::: "memory")

#define LDSM4(r0, r1, r2, r3, addr) \
    asm volatile("ldmatrix.sync.aligned.m8n8.x4.shared.b16 {%0,%1,%2,%3}, [%4];" \
                 : "=r"(r0), "=r"(r1), "=r"(r2), "=r"(r3) : "r"(addr))

#define MMA16816(d, a, b0, b1) \
    asm volatile("mma.sync.aligned.m16n8k16.row.col.f32.bf16.bf16.f32 " \
                 "{%0,%1,%2,%3}, {%4,%5,%6,%7}, {%8,%9}, {%0,%1,%2,%3};" \
                 : "+f"((d)[0]), "+f"((d)[1]), "+f"((d)[2]), "+f"((d)[3]) \
                 : "r"((a)[0]), "r"((a)[1]), "r"((a)[2]), "r"((a)[3]), \
                   "r"(b0), "r"(b1))

__device__ __forceinline__ void split2(float a, float b, u32& hi, u32& lo) {
    asm("cvt.rn.bf16x2.f32 %0,%1,%2;" : "=r"(hi) : "f"(b), "f"(a));
    float ra = a - __uint_as_float(hi << 16);
    float rb = b - __uint_as_float(hi & 0xFFFF0000u);
    asm("cvt.rn.bf16x2.f32 %0,%1,%2;" : "=r"(lo) : "f"(rb), "f"(ra));
}

// ---------------------------------------------------------------------------
// Kernel 1: blocks [0,128): h = inp@W, f1/f2 (prescaled), H^T bf16 planes.
//           blocks [128,384): adj -> ballot bitmask.  (validated R7/R8)
// ---------------------------------------------------------------------------
#define PR2 130
#define KHF_SMEM (FF * FF * 4 + FF * PR2 * 8)

__global__ void __launch_bounds__(512) k_hf(const float* __restrict__ inp,
                                            const float* __restrict__ W,
                                            const float* __restrict__ a,
                                            const int* __restrict__ adj) {
    const int t = threadIdx.x;
    const float L2E = 1.44269504089f;

    if (blockIdx.x >= 128) {
        const int gw = (blockIdx.x - 128) * 16 + (t >> 5);
        const int lane = t & 31;
        const int4* src = (const int4*)adj + (size_t)gw * 64 * 32 + lane;
        uint4* dst = g_mask + (size_t)gw * 64;
#pragma unroll 1
        for (int r = 0; r < 8; ++r) {
            int4 v[8];
#pragma unroll
            for (int s = 0; s < 8; ++s) v[s] = src[(r * 8 + s) * 32];
#pragma unroll
            for (int s = 0; s < 8; ++s) {
                uint4 m;
                m.x = __ballot_sync(0xffffffffu, v[s].x > 0);
                m.y = __ballot_sync(0xffffffffu, v[s].y > 0);
                m.z = __ballot_sync(0xffffffffu, v[s].z > 0);
                m.w = __ballot_sync(0xffffffffu, v[s].w > 0);
                if (lane == 0) dst[r * 8 + s] = m;
            }
        }
        return;
    }

    extern __shared__ char smem[];
    float*  Ws   = (float*)smem;
    float2* IsT2 = (float2*)(smem + FF * FF * 4);

    const int row0 = blockIdx.x * 128;
    const int tx   = t & 7;
    const int ty   = t >> 3;

    ((float4*)Ws)[t]       = ((const float4*)W)[t];
    ((float4*)Ws)[t + 512] = ((const float4*)W)[t + 512];
#pragma unroll
    for (int q = 0; q < 4; ++q) {
        int idx = t + 512 * q;
        int r = idx >> 4, k4 = (idx & 15) * 4;
        float4 v = ((const float4*)(inp + (size_t)(row0 + r) * FF))[idx & 15];
        IsT2[(k4 + 0) * PR2 + r] = make_float2(v.x, v.x);
        IsT2[(k4 + 1) * PR2 + r] = make_float2(v.y, v.y);
        IsT2[(k4 + 2) * PR2 + r] = make_float2(v.z, v.z);
        IsT2[(k4 + 3) * PR2 + r] = make_float2(v.w, v.w);
    }
    __syncthreads();

    u64 acc[2][4] = {};
#pragma unroll 8
    for (int k = 0; k < FF; ++k) {
        ulonglong2 pp = *(const ulonglong2*)&IsT2[k * PR2 + ty * 2];
        u64 pd[2] = {pp.x, pp.y};
        ulonglong2 h0 = *(const ulonglong2*)&Ws[k * FF + tx * 8];
        ulonglong2 h1 = *(const ulonglong2*)&Ws[k * FF + tx * 8 + 4];
        u64 hp[4] = {h0.x, h0.y, h1.x, h1.y};
#pragma unroll
        for (int r = 0; r < 2; ++r)
#pragma unroll
            for (int c = 0; c < 4; ++c) FMA2(acc[r][c], pd[r], hp[c], acc[r][c]);
    }

    float hv[2][8];
#pragma unroll
    for (int r = 0; r < 2; ++r)
#pragma unroll
        for (int c = 0; c < 4; ++c)
            UNPACK2(hv[r][2 * c], hv[r][2 * c + 1], acc[r][c]);

    float av1[8], av2[8];
#pragma unroll
    for (int c = 0; c < 8; ++c) {
        av1[c] = __ldg(a + tx * 8 + c);
        av2[c] = __ldg(a + 64 + tx * 8 + c);
    }
#pragma unroll
    for (int r = 0; r < 2; ++r) {
        float s1 = 0.f, s2 = 0.f;
#pragma unroll
        for (int c = 0; c < 8; ++c) { s1 += hv[r][c] * av1[c]; s2 += hv[r][c] * av2[c]; }
#pragma unroll
        for (int o = 1; o < 8; o <<= 1) {
            s1 += __shfl_xor_sync(0xffffffffu, s1, o);
            s2 += __shfl_xor_sync(0xffffffffu, s2, o);
        }
        if (tx == 0) {
            g_f1[row0 + ty * 2 + r] = s1 * L2E;
            g_f2[row0 + ty * 2 + r] = s2 * L2E;
        }
    }

    __syncthreads();
    u32* trH = (u32*)(smem + 16384);
    u32* trL = trH + 64 * 68;
#pragma unroll
    for (int c = 0; c < 8; ++c) {
        const int n = tx * 8 + c;
        u32 hi, lo;
        split2(hv[0][c], hv[1][c], hi, lo);
        trH[n * 68 + ty] = hi;
        trL[n * 68 + ty] = lo;
    }
    __syncthreads();

    const int b     = row0 >> 11;
    const int jloc0 = row0 & 2047;
    float4* dH = (float4*)g_hTh;
    float4* dL = (float4*)g_hTl;
#pragma unroll
    for (int u = 0; u < 2; ++u) {
        const int idx = t + 512 * u;
        const int n = idx >> 4, c = idx & 15;
        const int gidx = (b * 64 + n) * 256 + (jloc0 >> 3) + c;
        dH[gidx] = *(const float4*)(trH + n * 68 + c * 4);
        dL[gidx] = *(const float4*)(trL + n * 68 + c * 4);
    }
}

// ---------------------------------------------------------------------------
// Kernel 2: pipelined attention. 256 CTAs x 256 threads, 1 CTA/SM (164KB smem).
// Double-buffered P+HT; ONE barrier per tile: MMA(t) overlaps scores(t+1).
// ---------------------------------------------------------------------------
#define PSTRIDE 272
#define BUFSZ   69632          // per stage: PH(0) PL(17408) HTH(34816) HTL(52224)
#define OF_PL   17408
#define OF_HTH  34816
#define OF_HTL  52224
#define SM_MSK  139264
#define SM_F2   155648
#define SM_SR   163840
#define ATTN_SMEM 164096

__global__ void __launch_bounds__(256, 1) k_attn(float* __restrict__ out) {
    extern __shared__ char smem[];
    const u32 sb = smem_u32(smem);
    const int t = threadIdx.x;
    const int w = t >> 5, lane = t & 31;
    const int i0 = blockIdx.x * 64;
    const int b  = blockIdx.y;

    uint4* msk_s = (uint4*)(smem + SM_MSK);
    float* f2s   = (float*)(smem + SM_F2);

    const float4* hsH = (const float4*)g_hTh + (size_t)b * 64 * 256;
    const float4* hsL = (const float4*)g_hTl + (size_t)b * 64 * 256;
    const int stg_n = t >> 4, stg_c = t & 15;

    // ---- prologue: masks + f2 + HT(0) ----
    {
        const uint4* gm = g_mask + (size_t)(b * NN + i0) * 16;
#pragma unroll
        for (int u = 0; u < 4; ++u) msk_s[t + 256 * u] = gm[t + 256 * u];
        const float4* f2g = (const float4*)(g_f2 + (size_t)b * NN);
#pragma unroll
        for (int u = 0; u < 2; ++u) ((float4*)f2s)[t + 256 * u] = f2g[t + 256 * u];
#pragma unroll
        for (int u = 0; u < 4; ++u) {
            const int n = stg_n + 16 * u;
            const int g = (n << 8) + stg_c;
            const u32 so = (u32)(n * PSTRIDE + stg_c * 16);
            CPASYNC16(sb + OF_HTH + so, hsH + g);
            CPASYNC16(sb + OF_HTL + so, hsL + g);
        }
        CPCOMMIT();
    }

    float f1r[8];
#pragma unroll
    for (int q = 0; q < 8; ++q) f1r[q] = __ldg(g_f1 + b * NN + i0 + 8 * w + q);
    float Sacc[8];
#pragma unroll
    for (int q = 0; q < 8; ++q) Sacc[q] = 0.f;

    const int m0 = (w & 3) * 16;
    const int n0 = (w >> 2) * 32;
    const u32 rowsel = (u32)(lane & 15);
    const u32 colsel = (u32)((lane >> 4) * 16);
    const u32 aA  = sb + (m0 + rowsel) * PSTRIDE + colsel;
    const u32 aB0 = sb + OF_HTH + (n0 + rowsel) * PSTRIDE + colsel;
    const u32 aB1 = aB0 + 16 * PSTRIDE;
    float d[4][4] = {};

    __syncthreads();   // masks/f2 visible

    // ---- scores for tile 0 into buffer 0 ----
    {
        char* pbase = smem;
        const float4 f2v = *(const float4*)(f2s + lane * 4);
#pragma unroll
        for (int q = 0; q < 8; ++q) {
            const uint4 m = msk_s[(8 * w + q) * 16];
            const float f1v = f1r[q];
            float x0 = f1v + f2v.x; x0 = fmaxf(x0, 0.2f * x0);
            float x1 = f1v + f2v.y; x1 = fmaxf(x1, 0.2f * x1);
            float x2 = f1v + f2v.z; x2 = fmaxf(x2, 0.2f * x2);
            float x3 = f1v + f2v.w; x3 = fmaxf(x3, 0.2f * x3);
            const float p0 = ((m.x >> lane) & 1u) ? ex2(x0) : 0.f;
            const float p1 = ((m.y >> lane) & 1u) ? ex2(x1) : 0.f;
            const float p2 = ((m.z >> lane) & 1u) ? ex2(x2) : 0.f;
            const float p3 = ((m.w >> lane) & 1u) ? ex2(x3) : 0.f;
            Sacc[q] += (p0 + p1) + (p2 + p3);
            u32 h0, l0, h1, l1;
            split2(p0, p1, h0, l0);
            split2(p2, p3, h1, l1);
            char* prow = pbase + (8 * w + q) * PSTRIDE + lane * 8;
            *(uint2*)(prow)         = make_uint2(h0, h1);
            *(uint2*)(prow + OF_PL) = make_uint2(l0, l1);
        }
    }
    CPWAIT0();
    __syncthreads();   // P(0) + HT(0) ready

    // ---- pipelined main loop: MMA(tt) overlapped with scores(tt+1) ----
    for (int tt = 0; tt < 16; ++tt) {
        const u32 stoff  = (u32)((tt & 1) * BUFSZ);
        const u32 stoffN = (u32)(((tt + 1) & 1) * BUFSZ);

        // stage HT(tt+1) into the other buffer (async, waits before barrier)
        if (tt < 15) {
#pragma unroll
            for (int u = 0; u < 4; ++u) {
                const int n = stg_n + 16 * u;
                const int g = (n << 8) + ((tt + 1) << 4) + stg_c;
                const u32 so = (u32)(n * PSTRIDE + stg_c * 16);
                CPASYNC16(sb + stoffN + OF_HTH + so, hsH + g);
                CPASYNC16(sb + stoffN + OF_HTL + so, hsL + g);
            }
            CPCOMMIT();
        }

        // MMA on buffer tt&1 (issues stream into tensor pipe)
#pragma unroll
        for (int kk = 0; kk < 8; ++kk) {
            const u32 off = stoff + kk * 32;
            u32 ah[4], al[4], bh0[4], bh1[4], bl0[4], bl1[4];
            LDSM4(ah[0], ah[1], ah[2], ah[3], aA + off);
            LDSM4(al[0], al[1], al[2], al[3], aA + OF_PL + off);
            LDSM4(bh0[0], bh0[1], bh0[2], bh0[3], aB0 + off);
            LDSM4(bh1[0], bh1[1], bh1[2], bh1[3], aB1 + off);
            LDSM4(bl0[0], bl0[1], bl0[2], bl0[3], aB0 + (OF_HTL - OF_HTH) + off);
            LDSM4(bl1[0], bl1[1], bl1[2], bl1[3], aB1 + (OF_HTL - OF_HTH) + off);
            MMA16816(d[0], ah, bh0[0], bh0[2]);
            MMA16816(d[1], ah, bh0[1], bh0[3]);
            MMA16816(d[2], ah, bh1[0], bh1[2]);
            MMA16816(d[3], ah, bh1[1], bh1[3]);
            MMA16816(d[0], al, bh0[0], bh0[2]);
            MMA16816(d[1], al, bh0[1], bh0[3]);
            MMA16816(d[2], al, bh1[0], bh1[2]);
            MMA16816(d[3], al, bh1[1], bh1[3]);
            MMA16816(d[0], ah, bl0[0], bl0[2]);
            MMA16816(d[1], ah, bl0[1], bl0[3]);
            MMA16816(d[2], ah, bl1[0], bl1[2]);
            MMA16816(d[3], ah, bl1[1], bl1[3]);
        }

        // scores(tt+1) into the other buffer (alu/mufu pipes, overlaps MMA)
        if (tt < 15) {
            char* pbase = smem + stoffN;
            const float4 f2v = *(const float4*)(f2s + ((tt + 1) << 7) + lane * 4);
#pragma unroll
            for (int q = 0; q < 8; ++q) {
                const uint4 m = msk_s[(8 * w + q) * 16 + tt + 1];
                const float f1v = f1r[q];
                float x0 = f1v + f2v.x; x0 = fmaxf(x0, 0.2f * x0);
                float x1 = f1v + f2v.y; x1 = fmaxf(x1, 0.2f * x1);
                float x2 = f1v + f2v.z; x2 = fmaxf(x2, 0.2f * x2);
                float x3 = f1v + f2v.w; x3 = fmaxf(x3, 0.2f * x3);
                const float p0 = ((m.x >> lane) & 1u) ? ex2(x0) : 0.f;
                const float p1 = ((m.y >> lane) & 1u) ? ex2(x1) : 0.f;
                const float p2 = ((m.z >> lane) & 1u) ? ex2(x2) : 0.f;
                const float p3 = ((m.w >> lane) & 1u) ? ex2(x3) : 0.f;
                Sacc[q] += (p0 + p1) + (p2 + p3);
                u32 h0, l0, h1, l1;
                split2(p0, p1, h0, l0);
                split2(p2, p3, h1, l1);
                char* prow = pbase + (8 * w + q) * PSTRIDE + lane * 8;
                *(uint2*)(prow)         = make_uint2(h0, h1);
                *(uint2*)(prow + OF_PL) = make_uint2(l0, l1);
            }
        }

        CPWAIT0();
        __syncthreads();   // single barrier: P/HT(tt+1) ready, MMA(tt) reads done
    }

    // ---- softmax denominators ----
    float* Srow = (float*)(smem + SM_SR);
#pragma unroll
    for (int q = 0; q < 8; ++q) {
        float s = Sacc[q];
#pragma unroll
        for (int o = 1; o < 32; o <<= 1) s += __shfl_xor_sync(0xffffffffu, s, o);
        if (lane == q) Srow[8 * w + q] = s;
    }
    __syncthreads();

    // ---- epilogue ----
    const int r0 = m0 + (lane >> 2);
    const int r1 = r0 + 8;
    const float inv0 = 1.0f / Srow[r0];
    const float inv1 = 1.0f / Srow[r1];
    float* o0 = out + ((size_t)(b * NN + i0 + r0)) * FF + n0 + (lane & 3) * 2;
    float* o1 = out + ((size_t)(b * NN + i0 + r1)) * FF + n0 + (lane & 3) * 2;
#pragma unroll
    for (int nb = 0; nb < 4; ++nb) {
        float v0 = d[nb][0] * inv0, v1 = d[nb][1] * inv0;
        float v2 = d[nb][2] * inv1, v3 = d[nb][3] * inv1;
        v0 = v0 > 0.f ? v0 : expm1f(v0);
        v1 = v1 > 0.f ? v1 : expm1f(v1);
        v2 = v2 > 0.f ? v2 : expm1f(v2);
        v3 = v3 > 0.f ? v3 : expm1f(v3);
        *(float2*)(o0 + nb * 8) = make_float2(v0, v1);
        *(float2*)(o1 + nb * 8) = make_float2(v2, v3);
    }
}

// ---------------------------------------------------------------------------
extern "C" void kernel_launch(void* const* d_in, const int* in_sizes, int n_in,
                              void* d_out, int out_size) {
    const float* inp = (const float*)d_in[0];
    const int*   adj = (const int*)d_in[1];
    const float* W   = (const float*)d_in[2];
    const float* a   = (const float*)d_in[3];
    float* out = (float*)d_out;

    cudaFuncSetAttribute(k_hf, cudaFuncAttributeMaxDynamicSharedMemorySize, KHF_SMEM);
    cudaFuncSetAttribute(k_attn, cudaFuncAttributeMaxDynamicSharedMemorySize, ATTN_SMEM);

    k_hf<<<128 + 256, 512, KHF_SMEM>>>(inp, W, a, adj);
    dim3 g(NN / 64, BB);
    k_attn<<<g, 256, ATTN_SMEM>>>(out);
}

// round 10
// speedup vs baseline: 1.0698x; 1.0698x over previous
#include <cuda_runtime.h>
#include <cuda_bf16.h>
#include <math.h>
#include <stdint.h>

#define BB 8
#define NN 2048
#define FF 64

typedef unsigned long long u64;
typedef unsigned int u32;

// -------------------- device scratch --------------------
// per-node exp factors: A=exp(f1), a=exp(0.2 f1); B=exp(f2), b=exp(0.2 f2)
__device__ __align__(16) float2 g_eA[BB * NN];
__device__ __align__(16) float2 g_eB[BB * NN];
__device__ __align__(16) u32 g_hTh[BB * FF * (NN / 2)];
__device__ __align__(16) u32 g_hTl[BB * FF * (NN / 2)];
__device__ __align__(16) uint4 g_mask[BB * NN * 16];

// -------------------- PTX helpers --------------------
#define FMA2(d, a, b, c) \
    asm("fma.rn.f32x2 %0,%1,%2,%3;" : "=l"(d) : "l"(a), "l"(b), "l"(c))
#define UNPACK2(lo, hi, s) \
    asm("mov.b64 {%0,%1},%2;" : "=f"(lo), "=f"(hi) : "l"(s))

__device__ __forceinline__ float ex2(float x) {
    float r; asm("ex2.approx.ftz.f32 %0,%1;" : "=f"(r) : "f"(x)); return r;
}
__device__ __forceinline__ u32 smem_u32(const void* p) {
    u32 a;
    asm("{.reg .u64 t; cvta.to.shared.u64 t, %1; cvt.u32.u64 %0, t;}"
        : "=r"(a) : "l"(p));
    return a;
}

#define CPASYNC16(saddr, gptr) \
    asm volatile("cp.async.ca.shared.global [%0], [%1], 16;" \
                 :: "r"(saddr), "l"(gptr) : "memory")
#define CPCOMMIT() asm volatile("cp.async.commit_group;" ::: "memory")
#define CPWAIT0()  asm volatile("cp.async.wait_group 0;" ::: "memory")

#define LDSM4(r0, r1, r2, r3, addr) \
    asm volatile("ldmatrix.sync.aligned.m8n8.x4.shared.b16 {%0,%1,%2,%3}, [%4];" \
                 : "=r"(r0), "=r"(r1), "=r"(r2), "=r"(r3) : "r"(addr))

#define MMA16816(d, a, b0, b1) \
    asm volatile("mma.sync.aligned.m16n8k16.row.col.f32.bf16.bf16.f32 " \
                 "{%0,%1,%2,%3}, {%4,%5,%6,%7}, {%8,%9}, {%0,%1,%2,%3};" \
                 : "+f"((d)[0]), "+f"((d)[1]), "+f"((d)[2]), "+f"((d)[3]) \
                 : "r"((a)[0]), "r"((a)[1]), "r"((a)[2]), "r"((a)[3]), \
                   "r"(b0), "r"(b1))

__device__ __forceinline__ void split2(float a, float b, u32& hi, u32& lo) {
    asm("cvt.rn.bf16x2.f32 %0,%1,%2;" : "=r"(hi) : "f"(b), "f"(a));
    float ra = a - __uint_as_float(hi << 16);
    float rb = b - __uint_as_float(hi & 0xFFFF0000u);
    asm("cvt.rn.bf16x2.f32 %0,%1,%2;" : "=r"(lo) : "f"(rb), "f"(ra));
}

// ---------------------------------------------------------------------------
// Kernel 1: blocks [0,128): h = inp@W, per-node exp factors, H^T bf16 planes.
//           blocks [128,384): adj -> ballot bitmask.
// ---------------------------------------------------------------------------
#define PR2 130
#define KHF_SMEM (FF * FF * 4 + FF * PR2 * 8)

__global__ void __launch_bounds__(512) k_hf(const float* __restrict__ inp,
                                            const float* __restrict__ W,
                                            const float* __restrict__ a,
                                            const int* __restrict__ adj) {
    const int t = threadIdx.x;
    const float L2E = 1.44269504089f;

    if (blockIdx.x >= 128) {
        const int gw = (blockIdx.x - 128) * 16 + (t >> 5);
        const int lane = t & 31;
        const int4* src = (const int4*)adj + (size_t)gw * 64 * 32 + lane;
        uint4* dst = g_mask + (size_t)gw * 64;
#pragma unroll 1
        for (int r = 0; r < 8; ++r) {
            int4 v[8];
#pragma unroll
            for (int s = 0; s < 8; ++s) v[s] = src[(r * 8 + s) * 32];
#pragma unroll
            for (int s = 0; s < 8; ++s) {
                uint4 m;
                m.x = __ballot_sync(0xffffffffu, v[s].x > 0);
                m.y = __ballot_sync(0xffffffffu, v[s].y > 0);
                m.z = __ballot_sync(0xffffffffu, v[s].z > 0);
                m.w = __ballot_sync(0xffffffffu, v[s].w > 0);
                if (lane == 0) dst[r * 8 + s] = m;
            }
        }
        return;
    }

    extern __shared__ char smem[];
    float*  Ws   = (float*)smem;
    float2* IsT2 = (float2*)(smem + FF * FF * 4);

    const int row0 = blockIdx.x * 128;
    const int tx   = t & 7;
    const int ty   = t >> 3;

    ((float4*)Ws)[t]       = ((const float4*)W)[t];
    ((float4*)Ws)[t + 512] = ((const float4*)W)[t + 512];
#pragma unroll
    for (int q = 0; q < 4; ++q) {
        int idx = t + 512 * q;
        int r = idx >> 4, k4 = (idx & 15) * 4;
        float4 v = ((const float4*)(inp + (size_t)(row0 + r) * FF))[idx & 15];
        IsT2[(k4 + 0) * PR2 + r] = make_float2(v.x, v.x);
        IsT2[(k4 + 1) * PR2 + r] = make_float2(v.y, v.y);
        IsT2[(k4 + 2) * PR2 + r] = make_float2(v.z, v.z);
        IsT2[(k4 + 3) * PR2 + r] = make_float2(v.w, v.w);
    }
    __syncthreads();

    u64 acc[2][4] = {};
#pragma unroll 8
    for (int k = 0; k < FF; ++k) {
        ulonglong2 pp = *(const ulonglong2*)&IsT2[k * PR2 + ty * 2];
        u64 pd[2] = {pp.x, pp.y};
        ulonglong2 h0 = *(const ulonglong2*)&Ws[k * FF + tx * 8];
        ulonglong2 h1 = *(const ulonglong2*)&Ws[k * FF + tx * 8 + 4];
        u64 hp[4] = {h0.x, h0.y, h1.x, h1.y};
#pragma unroll
        for (int r = 0; r < 2; ++r)
#pragma unroll
            for (int c = 0; c < 4; ++c) FMA2(acc[r][c], pd[r], hp[c], acc[r][c]);
    }

    float hv[2][8];
#pragma unroll
    for (int r = 0; r < 2; ++r)
#pragma unroll
        for (int c = 0; c < 4; ++c)
            UNPACK2(hv[r][2 * c], hv[r][2 * c + 1], acc[r][c]);

    float av1[8], av2[8];
#pragma unroll
    for (int c = 0; c < 8; ++c) {
        av1[c] = __ldg(a + tx * 8 + c);
        av2[c] = __ldg(a + 64 + tx * 8 + c);
    }
#pragma unroll
    for (int r = 0; r < 2; ++r) {
        float s1 = 0.f, s2 = 0.f;
#pragma unroll
        for (int c = 0; c < 8; ++c) { s1 += hv[r][c] * av1[c]; s2 += hv[r][c] * av2[c]; }
#pragma unroll
        for (int o = 1; o < 8; o <<= 1) {
            s1 += __shfl_xor_sync(0xffffffffu, s1, o);
            s2 += __shfl_xor_sync(0xffffffffu, s2, o);
        }
        if (tx == 0) {
            const int row = row0 + ty * 2 + r;
            g_eA[row] = make_float2(ex2(s1 * L2E), ex2(0.2f * s1 * L2E));
            g_eB[row] = make_float2(ex2(s2 * L2E), ex2(0.2f * s2 * L2E));
        }
    }

    __syncthreads();
    u32* trH = (u32*)(smem + 16384);
    u32* trL = trH + 64 * 68;
#pragma unroll
    for (int c = 0; c < 8; ++c) {
        const int n = tx * 8 + c;
        u32 hi, lo;
        split2(hv[0][c], hv[1][c], hi, lo);
        trH[n * 68 + ty] = hi;
        trL[n * 68 + ty] = lo;
    }
    __syncthreads();

    const int b     = row0 >> 11;
    const int jloc0 = row0 & 2047;
    float4* dH = (float4*)g_hTh;
    float4* dL = (float4*)g_hTl;
#pragma unroll
    for (int u = 0; u < 2; ++u) {
        const int idx = t + 512 * u;
        const int n = idx >> 4, c = idx & 15;
        const int gidx = (b * 64 + n) * 256 + (jloc0 >> 3) + c;
        dH[gidx] = *(const float4*)(trH + n * 68 + c * 4);
        dL[gidx] = *(const float4*)(trL + n * 68 + c * 4);
    }
}

// ---------------------------------------------------------------------------
// Kernel 2: attention via mma.sync, MUFU-free scores: p = mask?max(AB, ab):0.
// 256 CTAs x 256 threads, 2 CTAs/SM. cp.async HT staging, round-robin MMA.
// ---------------------------------------------------------------------------
#define PSTRIDE 272
#define SM_PH  0
#define SM_PL  17408
#define SM_HTH 34816
#define SM_HTL 52224
#define SM_MSK 69632
#define SM_EB  86016
#define SM_SR  102400
#define ATTN_SMEM 102656

__global__ void __launch_bounds__(256, 2) k_attn(float* __restrict__ out) {
    extern __shared__ char smem[];
    const u32 sb = smem_u32(smem);
    const int t = threadIdx.x;
    const int w = t >> 5, lane = t & 31;
    const int i0 = blockIdx.x * 64;
    const int b  = blockIdx.y;

    uint4*  msk_s = (uint4*)(smem + SM_MSK);
    float4* ebs4  = (float4*)(smem + SM_EB);   // (B,b) pairs, 2 j per float4

    // ---- prologue: masks + eB pairs ----
    {
        const uint4* gm = g_mask + (size_t)(b * NN + i0) * 16;
#pragma unroll
        for (int u = 0; u < 4; ++u) msk_s[t + 256 * u] = gm[t + 256 * u];
        const float4* ebg = (const float4*)(g_eB + (size_t)b * NN);
#pragma unroll
        for (int u = 0; u < 4; ++u) ebs4[t + 256 * u] = ebg[t + 256 * u];
    }

    float Ai[8], ai[8];
#pragma unroll
    for (int q = 0; q < 8; ++q) {
        float2 e = __ldg(&g_eA[b * NN + i0 + 8 * w + q]);
        Ai[q] = e.x; ai[q] = e.y;
    }
    float Sacc[8];
#pragma unroll
    for (int q = 0; q < 8; ++q) Sacc[q] = 0.f;

    const int m0 = (w & 3) * 16;
    const int n0 = (w >> 2) * 32;
    const u32 rowsel = (u32)(lane & 15);
    const u32 colsel = (u32)((lane >> 4) * 16);
    const u32 aA  = sb + SM_PH  + (m0 + rowsel) * PSTRIDE + colsel;
    const u32 aB0 = sb + SM_HTH + (n0 + rowsel) * PSTRIDE + colsel;
    const u32 aB1 = aB0 + 16 * PSTRIDE;
    float d[4][4] = {};

    const float4* hsH = (const float4*)g_hTh + (size_t)b * 64 * 256;
    const float4* hsL = (const float4*)g_hTl + (size_t)b * 64 * 256;
    const int stg_n = t >> 4, stg_c = t & 15;

    for (int tt = 0; tt < 16; ++tt) {
        __syncthreads();   // all reads of previous tile done; prologue visible

        // ---- HT tile via cp.async (completes under score phase) ----
#pragma unroll
        for (int u = 0; u < 4; ++u) {
            const int n = stg_n + 16 * u;
            const int g = (n << 8) + (tt << 4) + stg_c;
            const u32 so = (u32)(n * PSTRIDE + stg_c * 16);
            CPASYNC16(sb + SM_HTH + so, hsH + g);
            CPASYNC16(sb + SM_HTL + so, hsL + g);
        }
        CPCOMMIT();

        // ---- scores: p = mask ? max(A*B, a*b) : 0 (no MUFU) ----
        const float4 eb01 = ebs4[(tt << 6) + (lane << 1)];
        const float4 eb23 = ebs4[(tt << 6) + (lane << 1) + 1];
#pragma unroll
        for (int q = 0; q < 8; ++q) {
            const uint4 m = msk_s[(8 * w + q) * 16 + tt];
            const float Av = Ai[q], av = ai[q];
            float p0 = fmaxf(Av * eb01.x, av * eb01.y);
            float p1 = fmaxf(Av * eb01.z, av * eb01.w);
            float p2 = fmaxf(Av * eb23.x, av * eb23.y);
            float p3 = fmaxf(Av * eb23.z, av * eb23.w);
            p0 = ((m.x >> lane) & 1u) ? p0 : 0.f;
            p1 = ((m.y >> lane) & 1u) ? p1 : 0.f;
            p2 = ((m.z >> lane) & 1u) ? p2 : 0.f;
            p3 = ((m.w >> lane) & 1u) ? p3 : 0.f;
            Sacc[q] += (p0 + p1) + (p2 + p3);
            u32 h0, l0, h1, l1;
            split2(p0, p1, h0, l0);
            split2(p2, p3, h1, l1);
            char* prow = smem + (8 * w + q) * PSTRIDE + lane * 8;
            *(uint2*)(prow + SM_PH) = make_uint2(h0, h1);
            *(uint2*)(prow + SM_PL) = make_uint2(l0, l1);
        }
        CPWAIT0();
        __syncthreads();   // P + HT visible

        // ---- MMA: round-robin accumulators ----
#pragma unroll
        for (int kk = 0; kk < 8; ++kk) {
            const u32 off = kk * 32;
            u32 ah[4], al[4], bh0[4], bh1[4], bl0[4], bl1[4];
            LDSM4(ah[0], ah[1], ah[2], ah[3], aA + off);
            LDSM4(al[0], al[1], al[2], al[3], aA + (SM_PL - SM_PH) + off);
            LDSM4(bh0[0], bh0[1], bh0[2], bh0[3], aB0 + off);
            LDSM4(bh1[0], bh1[1], bh1[2], bh1[3], aB1 + off);
            LDSM4(bl0[0], bl0[1], bl0[2], bl0[3], aB0 + (SM_HTL - SM_HTH) + off);
            LDSM4(bl1[0], bl1[1], bl1[2], bl1[3], aB1 + (SM_HTL - SM_HTH) + off);
            MMA16816(d[0], ah, bh0[0], bh0[2]);
            MMA16816(d[1], ah, bh0[1], bh0[3]);
            MMA16816(d[2], ah, bh1[0], bh1[2]);
            MMA16816(d[3], ah, bh1[1], bh1[3]);
            MMA16816(d[0], al, bh0[0], bh0[2]);
            MMA16816(d[1], al, bh0[1], bh0[3]);
            MMA16816(d[2], al, bh1[0], bh1[2]);
            MMA16816(d[3], al, bh1[1], bh1[3]);
            MMA16816(d[0], ah, bl0[0], bl0[2]);
            MMA16816(d[1], ah, bl0[1], bl0[3]);
            MMA16816(d[2], ah, bl1[0], bl1[2]);
            MMA16816(d[3], ah, bl1[1], bl1[3]);
        }
    }

    // ---- softmax denominators ----
    float* Srow = (float*)(smem + SM_SR);
#pragma unroll
    for (int q = 0; q < 8; ++q) {
        float s = Sacc[q];
#pragma unroll
        for (int o = 1; o < 32; o <<= 1) s += __shfl_xor_sync(0xffffffffu, s, o);
        if (lane == q) Srow[8 * w + q] = s;
    }
    __syncthreads();

    // ---- epilogue ----
    const int r0 = m0 + (lane >> 2);
    const int r1 = r0 + 8;
    const float inv0 = 1.0f / Srow[r0];
    const float inv1 = 1.0f / Srow[r1];
    float* o0 = out + ((size_t)(b * NN + i0 + r0)) * FF + n0 + (lane & 3) * 2;
    float* o1 = out + ((size_t)(b * NN + i0 + r1)) * FF + n0 + (lane & 3) * 2;
#pragma unroll
    for (int nb = 0; nb < 4; ++nb) {
        float v0 = d[nb][0] * inv0, v1 = d[nb][1] * inv0;
        float v2 = d[nb][2] * inv1, v3 = d[nb][3] * inv1;
        v0 = v0 > 0.f ? v0 : expm1f(v0);
        v1 = v1 > 0.f ? v1 : expm1f(v1);
        v2 = v2 > 0.f ? v2 : expm1f(v2);
        v3 = v3 > 0.f ? v3 : expm1f(v3);
        *(float2*)(o0 + nb * 8) = make_float2(v0, v1);
        *(float2*)(o1 + nb * 8) = make_float2(v2, v3);
    }
}

// ---------------------------------------------------------------------------
extern "C" void kernel_launch(void* const* d_in, const int* in_sizes, int n_in,
                              void* d_out, int out_size) {
    const float* inp = (const float*)d_in[0];
    const int*   adj = (const int*)d_in[1];
    const float* W   = (const float*)d_in[2];
    const float* a   = (const float*)d_in[3];
    float* out = (float*)d_out;

    cudaFuncSetAttribute(k_hf, cudaFuncAttributeMaxDynamicSharedMemorySize, KHF_SMEM);
    cudaFuncSetAttribute(k_attn, cudaFuncAttributeMaxDynamicSharedMemorySize, ATTN_SMEM);

    k_hf<<<128 + 256, 512, KHF_SMEM>>>(inp, W, a, adj);
    dim3 g(NN / 64, BB);
    k_attn<<<g, 256, ATTN_SMEM>>>(out);
}